// round 9
// baseline (speedup 1.0000x reference)
#include <cuda_runtime.h>
#include <cuda_fp16.h>
#include <math.h>
#include <stdint.h>

#define T_TOKENS 8192
#define D_DIM    1024
#define E_EXP    8
#define H_DIM    4096
#define MT_MAX   136
#define PAD_ROWS (MT_MAX * 128)
#define KC1      32              // D/32 k-chunks (phase 0)
#define KC2      128             // H/32 k-chunks (phase 1)
#define NT1      32              // H/128 n-tiles (phase 0)
#define NT2      8               // D/128 n-tiles (phase 1)
#define STG      24576           // bytes per pipeline stage: A_hi 8K | A_lo 8K | B 8K
#define SMEM_SZ  (4 * STG)       // 96 KB

// -------- device scratch (tile-contiguous fp16) --------
__device__ __align__(256) __half g_xg_hi[(size_t)PAD_ROWS * D_DIM];
__device__ __align__(256) __half g_xg_lo[(size_t)PAD_ROWS * D_DIM];
__device__ __align__(256) __half g_h_hi[(size_t)PAD_ROWS * H_DIM];
__device__ __align__(256) __half g_h_lo[(size_t)PAD_ROWS * H_DIM];
__device__ __align__(256) __half g_w1t[(size_t)E_EXP * D_DIM * H_DIM];
__device__ __align__(256) __half g_w2t[(size_t)E_EXP * D_DIM * H_DIM];

__device__ int   g_counts[E_EXP];
__device__ int   g_offsets[E_EXP];
__device__ int   g_cursors[E_EXP];
__device__ int   g_tok_e[T_TOKENS * 2];
__device__ float g_tok_g[T_TOKENS * 2];
__device__ int   g_assign_tok[PAD_ROWS];
__device__ float g_assign_gate[PAD_ROWS];
__device__ int   g_tile_e[MT_MAX];

// ---------------- PTX helpers (base-target sm_80+ features) ----------------
__device__ __forceinline__ uint32_t smem_u32(const void* p) {
    uint32_t a;
    asm("{ .reg .u64 t; cvta.to.shared.u64 t, %1; cvt.u32.u64 %0, t; }" : "=r"(a) : "l"(p));
    return a;
}
#define CP16(dst, src) \
    asm volatile("cp.async.cg.shared.global [%0], [%1], 16;" :: "r"(dst), "l"(src) : "memory")
#define CP_COMMIT() asm volatile("cp.async.commit_group;" ::: "memory")
#define CP_WAIT2()  asm volatile("cp.async.wait_group 2;" ::: "memory")

#define LDSM4(r0,r1,r2,r3,a) \
    asm volatile("ldmatrix.sync.aligned.m8n8.x4.shared.b16 {%0,%1,%2,%3},[%4];" \
        : "=r"(r0),"=r"(r1),"=r"(r2),"=r"(r3) : "r"(a))
#define LDSM4T(r0,r1,r2,r3,a) \
    asm volatile("ldmatrix.sync.aligned.m8n8.x4.trans.shared.b16 {%0,%1,%2,%3},[%4];" \
        : "=r"(r0),"=r"(r1),"=r"(r2),"=r"(r3) : "r"(a))

__device__ __forceinline__ void mma_f16(float* c, const uint32_t* a, const uint32_t* b) {
    asm volatile(
        "mma.sync.aligned.m16n8k16.row.col.f32.f16.f16.f32 "
        "{%0,%1,%2,%3},{%4,%5,%6,%7},{%8,%9},{%0,%1,%2,%3};"
        : "+f"(c[0]), "+f"(c[1]), "+f"(c[2]), "+f"(c[3])
        : "r"(a[0]), "r"(a[1]), "r"(a[2]), "r"(a[3]), "r"(b[0]), "r"(b[1]));
}

// split two fp32 into packed fp16 hi / fp16 lo (residual)
__device__ __forceinline__ void split2(float v0, float v1, uint32_t& hi, uint32_t& lo) {
    __half h0 = __float2half_rn(v0);
    __half h1 = __float2half_rn(v1);
    __half l0 = __float2half_rn(v0 - __half2float(h0));
    __half l1 = __float2half_rn(v1 - __half2float(h1));
    hi = ((uint32_t)__half_as_ushort(h1) << 16) | __half_as_ushort(h0);
    lo = ((uint32_t)__half_as_ushort(l1) << 16) | __half_as_ushort(l0);
}
// convert two fp32 to packed fp16
__device__ __forceinline__ uint32_t cvt2(float v0, float v1) {
    return ((uint32_t)__half_as_ushort(__float2half_rn(v1)) << 16)
         | __half_as_ushort(__float2half_rn(v0));
}

// ---------------- routing pipeline ----------------
__global__ void reset_kernel() {
    int i = blockIdx.x * blockDim.x + threadIdx.x;
    if (i < E_EXP) { g_counts[i] = 0; g_cursors[i] = 0; }
    if (i < PAD_ROWS) { g_assign_tok[i] = -1; g_assign_gate[i] = 0.f; }
}

__global__ void router_kernel(const float* __restrict__ x, const float* __restrict__ noise,
                              const float* __restrict__ Wg, const float* __restrict__ bg,
                              const float* __restrict__ Wn, const float* __restrict__ bn)
{
    __shared__ float sx[8][D_DIM];
    const int warp = threadIdx.x >> 5, lane = threadIdx.x & 31;
    const int t = blockIdx.x * 8 + warp;
    const float4* xr  = reinterpret_cast<const float4*>(x + (size_t)t * D_DIM);
    float4*       sxr = reinterpret_cast<float4*>(sx[warp]);
    for (int i = lane; i < D_DIM / 4; i += 32) sxr[i] = xr[i];
    __syncwarp();

    float lg[E_EXP], nz[E_EXP];
    #pragma unroll
    for (int e = 0; e < E_EXP; e++) {
        float ag = 0.f, an = 0.f;
        for (int d = lane; d < D_DIM; d += 32) {
            float xv = sx[warp][d];
            ag = fmaf(xv, Wg[d * E_EXP + e], ag);
            an = fmaf(xv, Wn[d * E_EXP + e], an);
        }
        #pragma unroll
        for (int o = 16; o > 0; o >>= 1) {
            ag += __shfl_down_sync(0xffffffffu, ag, o);
            an += __shfl_down_sync(0xffffffffu, an, o);
        }
        lg[e] = ag; nz[e] = an;
    }
    if (lane == 0) {
        float nv[E_EXP];
        #pragma unroll
        for (int e = 0; e < E_EXP; e++) {
            float z  = nz[e] + bn[e];
            float sp = fmaxf(z, 0.f) + log1pf(expf(-fabsf(z)));
            nv[e] = lg[e] + bg[e] + noise[(size_t)t * E_EXP + e] * sp;
        }
        int e1 = 0; float v1 = nv[0];
        #pragma unroll
        for (int e = 1; e < E_EXP; e++) if (nv[e] > v1) { v1 = nv[e]; e1 = e; }
        int e2 = -1; float v2 = -INFINITY;
        #pragma unroll
        for (int e = 0; e < E_EXP; e++) if (e != e1 && nv[e] > v2) { v2 = nv[e]; e2 = e; }
        float ex = expf(v2 - v1);
        g_tok_e[2*t+0] = e1;  g_tok_g[2*t+0] = 1.f / (1.f + ex);
        g_tok_e[2*t+1] = e2;  g_tok_g[2*t+1] = ex  / (1.f + ex);
        atomicAdd(&g_counts[e1], 1);
        atomicAdd(&g_counts[e2], 1);
    }
}

__global__ void offsets_kernel() {
    if (threadIdx.x == 0) {
        int po = 0, t = 0;
        #pragma unroll
        for (int e = 0; e < E_EXP; e++) {
            g_offsets[e] = po;
            int ntl = (g_counts[e] + 127) >> 7;
            for (int j = 0; j < ntl; j++) g_tile_e[t++] = e;
            po += ntl << 7;
        }
        for (; t < MT_MAX; t++) g_tile_e[t] = -1;
    }
}

__global__ void scatter_kernel() {
    int t = blockIdx.x * blockDim.x + threadIdx.x;
    if (t >= T_TOKENS) return;
    #pragma unroll
    for (int k = 0; k < 2; k++) {
        int e = g_tok_e[2*t+k];
        int pos = g_offsets[e] + atomicAdd(&g_cursors[e], 1);
        g_assign_tok[pos]  = t;
        g_assign_gate[pos] = g_tok_g[2*t+k];
    }
}

// gather x rows -> [mtile][kc<32][m<128][k<32] fp16 hi/lo (tile-contiguous)
__global__ void gather_split_kernel(const float* __restrict__ x) {
    int slot = blockIdx.x;
    int tok = g_assign_tok[slot];
    int mtile = slot >> 7, r = slot & 127;
    int t = threadIdx.x;                 // 16B-output unit: 8 k-elements
    float v[8];
    if (tok >= 0) {
        const float4* p = reinterpret_cast<const float4*>(x + (size_t)tok * D_DIM + t * 8);
        float4 a = p[0], b = p[1];
        v[0]=a.x; v[1]=a.y; v[2]=a.z; v[3]=a.w; v[4]=b.x; v[5]=b.y; v[6]=b.z; v[7]=b.w;
    } else {
        #pragma unroll
        for (int j = 0; j < 8; j++) v[j] = 0.f;
    }
    uint32_t hi[4], lo[4];
    #pragma unroll
    for (int p = 0; p < 4; p++) split2(v[2*p], v[2*p+1], hi[p], lo[p]);
    int kc = t >> 2, kin = (t & 3) * 8;
    size_t o = (((size_t)mtile * KC1 + kc) * 128 + r) * 32 + kin;
    *reinterpret_cast<uint4*>(g_xg_hi + o) = make_uint4(hi[0],hi[1],hi[2],hi[3]);
    *reinterpret_cast<uint4*>(g_xg_lo + o) = make_uint4(lo[0],lo[1],lo[2],lo[3]);
}

// W[e][K][N] -> [e][nt][kc][ki<32][n<128] fp16 (tile-contiguous convert)
__global__ void wsplit_kernel(const float* __restrict__ W, int which) {
    int NT   = which ? NT2 : NT1;
    int KC   = which ? KC2 : KC1;
    int Kdim = which ? H_DIM : D_DIM;
    int Ndim = which ? D_DIM : H_DIM;
    __half* dst = which ? g_w2t : g_w1t;

    size_t idx = (size_t)blockIdx.x * 256 + threadIdx.x;   // each: 8 n-elements
    int nu = idx & 15;             // 16 units per 128-n row
    size_t q = idx >> 4;
    int ki = q & 31; q >>= 5;
    int kc = (int)(q % KC); q /= KC;
    int nt = (int)(q % NT); int e = (int)(q / NT);
    if (e >= E_EXP) return;

    int k = kc * 32 + ki;
    const float* src = W + ((size_t)e * Kdim + k) * Ndim + nt * 128 + nu * 8;
    const float4* s4 = reinterpret_cast<const float4*>(src);
    float4 a = s4[0], b = s4[1];
    uint4 o4 = make_uint4(cvt2(a.x, a.y), cvt2(a.z, a.w), cvt2(b.x, b.y), cvt2(b.z, b.w));
    *reinterpret_cast<uint4*>(dst + idx * 8) = o4;
}

// ---------------- fp16x2 mma.sync grouped GEMM ----------------
// CTA: 128(M) x 128(N), K-chunk 32, 4-stage cp.async pipeline, 2 CTAs/SM.
// Stage layout: A_hi(8K) | A_lo(8K) | B(8K).
// A smem: [m<128][k<32], 64B rows, 16B-unit swizzle u^((m>>1)&3).
// B smem: [k<32][n<128], 256B rows, 16B-unit swizzle u^(k&7).
template<int PHASE>
__global__ __launch_bounds__(256, 2)
void gemm_mma(const float* __restrict__ bias, float* __restrict__ out)
{
    constexpr int KI = PHASE ? KC2 : KC1;
    constexpr int NT = PHASE ? NT2 : NT1;
    const int mtile = blockIdx.y;
    const int e = g_tile_e[mtile];
    if (e < 0) return;
    const int nt = blockIdx.x;

    extern __shared__ __align__(128) char smem[];
    const uint32_t sm0 = smem_u32(smem);
    const int tid = threadIdx.x, lane = tid & 31, w = tid >> 5;
    const int wm = (w & 3) * 32, wn = (w >> 2) * 64;

    const __half* Ah = PHASE ? g_h_hi : g_xg_hi;
    const __half* Al = PHASE ? g_h_lo : g_xg_lo;
    const __half* Bw = PHASE ? g_w2t  : g_w1t;
    const size_t abase = (size_t)mtile * KI * 4096;
    const size_t bbase = (size_t)(e * NT + nt) * KI * 4096;

    // cp.async dst offsets (loop-invariant per thread)
    uint32_t dA[2], dB[2];
    #pragma unroll
    for (int i = 0; i < 2; i++) {
        int idx = tid + 256 * i;
        int mA = idx >> 2, uA = idx & 3;
        dA[i] = mA * 64 + ((uA ^ ((mA >> 1) & 3)) << 4);
        int kB = idx >> 4, uB = idx & 15;
        dB[i] = kB * 256 + ((uB ^ (kB & 7)) << 4);
    }

    auto issue = [&](int c) {
        if (c < KI) {
            uint32_t sb = sm0 + (c & 3) * STG;
            size_t ao = abase + (size_t)c * 4096;
            size_t bo = bbase + (size_t)c * 4096;
            #pragma unroll
            for (int i = 0; i < 2; i++) {
                size_t el = (size_t)(tid + 256 * i) * 8;
                CP16(sb +         dA[i], Ah + ao + el);
                CP16(sb + 8192  + dA[i], Al + ao + el);
                CP16(sb + 16384 + dB[i], Bw + bo + el);
            }
        }
        CP_COMMIT();
    };

    // ldmatrix source offsets (per lane, precomputed)
    uint32_t offA[2][2], offB[4][2];
    {
        int j = lane >> 3, r = lane & 7;
        #pragma unroll
        for (int mt = 0; mt < 2; mt++)
            #pragma unroll
            for (int ks = 0; ks < 2; ks++) {
                int m = wm + mt * 16 + (j & 1) * 8 + r;
                int k = ks * 16 + (j >> 1) * 8;
                offA[mt][ks] = m * 64 + (((k >> 3) ^ ((m >> 1) & 3)) << 4);
            }
        #pragma unroll
        for (int nb = 0; nb < 4; nb++)
            #pragma unroll
            for (int ks = 0; ks < 2; ks++) {
                int k = ks * 16 + (j & 1) * 8 + r;
                int n = wn + nb * 16 + (j >> 1) * 8;
                offB[nb][ks] = k * 256 + (((n >> 3) ^ (k & 7)) << 4);
            }
    }

    float acc[2][8][4];
    #pragma unroll
    for (int a = 0; a < 2; a++)
        #pragma unroll
        for (int b = 0; b < 8; b++)
            #pragma unroll
            for (int c = 0; c < 4; c++) acc[a][b][c] = 0.f;

    issue(0); issue(1); issue(2);

    for (int i = 0; i < KI; i++) {
        CP_WAIT2();
        __syncthreads();
        issue(i + 3);
        uint32_t sb = sm0 + (i & 3) * STG;
        #pragma unroll
        for (int ks = 0; ks < 2; ks++) {
            uint32_t aH[2][4], aL[2][4], bF[8][2];
            #pragma unroll
            for (int mt = 0; mt < 2; mt++) {
                LDSM4(aH[mt][0], aH[mt][1], aH[mt][2], aH[mt][3], sb + offA[mt][ks]);
                LDSM4(aL[mt][0], aL[mt][1], aL[mt][2], aL[mt][3], sb + 8192 + offA[mt][ks]);
            }
            #pragma unroll
            for (int nb = 0; nb < 4; nb++)
                LDSM4T(bF[2*nb][0], bF[2*nb][1], bF[2*nb+1][0], bF[2*nb+1][1],
                       sb + 16384 + offB[nb][ks]);
            #pragma unroll
            for (int mt = 0; mt < 2; mt++)
                #pragma unroll
                for (int nb = 0; nb < 8; nb++) {
                    mma_f16(acc[mt][nb], aH[mt], bF[nb]);
                    mma_f16(acc[mt][nb], aL[mt], bF[nb]);
                }
        }
    }

    // ---------------- epilogue ----------------
    if (PHASE == 0) {
        // bias + relu + fp16-split -> g_h in phase-1 A layout [mtile][kc][m][k32]
        #pragma unroll
        for (int mt = 0; mt < 2; mt++) {
            int row0 = wm + mt * 16 + (lane >> 2);
            #pragma unroll
            for (int nb = 0; nb < 8; nb++) {
                int col = wn + nb * 8 + (lane & 3) * 2;
                int ng  = nt * 128 + col;
                float bv0 = __ldg(&bias[(size_t)e * H_DIM + ng]);
                float bv1 = __ldg(&bias[(size_t)e * H_DIM + ng + 1]);
                int kc2 = ng >> 5, kin = ng & 31;
                #pragma unroll
                for (int rr = 0; rr < 2; rr++) {
                    int m = row0 + rr * 8;
                    float v0 = fmaxf(acc[mt][nb][rr*2+0] + bv0, 0.f);
                    float v1 = fmaxf(acc[mt][nb][rr*2+1] + bv1, 0.f);
                    uint32_t ph, pl;
                    split2(v0, v1, ph, pl);
                    size_t o = (((size_t)mtile * KC2 + kc2) * 128 + m) * 32 + kin;
                    *reinterpret_cast<uint32_t*>(g_h_hi + o) = ph;
                    *reinterpret_cast<uint32_t*>(g_h_lo + o) = pl;
                }
            }
        }
    } else {
        // bias + gate + atomic combine into out
        #pragma unroll
        for (int mt = 0; mt < 2; mt++) {
            #pragma unroll
            for (int rr = 0; rr < 2; rr++) {
                int m = wm + mt * 16 + (lane >> 2) + rr * 8;
                int slot = mtile * 128 + m;
                int tok = __ldg(&g_assign_tok[slot]);
                if (tok < 0) continue;
                float gate = __ldg(&g_assign_gate[slot]);
                float* orow = out + (size_t)tok * D_DIM;
                #pragma unroll
                for (int nb = 0; nb < 8; nb++) {
                    int col = wn + nb * 8 + (lane & 3) * 2;
                    int ng  = nt * 128 + col;
                    float y0 = acc[mt][nb][rr*2+0] + __ldg(&bias[(size_t)e * D_DIM + ng]);
                    float y1 = acc[mt][nb][rr*2+1] + __ldg(&bias[(size_t)e * D_DIM + ng + 1]);
                    atomicAdd(&orow[ng],     gate * y0);
                    atomicAdd(&orow[ng + 1], gate * y1);
                }
            }
        }
    }
}

// ============================================================================
extern "C" void kernel_launch(void* const* d_in, const int* in_sizes, int n_in,
                              void* d_out, int out_size)
{
    const float* x     = (const float*)d_in[0];
    const float* noise = (const float*)d_in[1];
    const float* Wg    = (const float*)d_in[2];
    const float* bg    = (const float*)d_in[3];
    const float* Wn    = (const float*)d_in[4];
    const float* bn    = (const float*)d_in[5];
    const float* W1    = (const float*)d_in[6];
    const float* b1    = (const float*)d_in[7];
    const float* W2    = (const float*)d_in[8];
    const float* b2    = (const float*)d_in[9];
    float*       out   = (float*)d_out;

    cudaFuncSetAttribute(gemm_mma<0>, cudaFuncAttributeMaxDynamicSharedMemorySize, SMEM_SZ);
    cudaFuncSetAttribute(gemm_mma<1>, cudaFuncAttributeMaxDynamicSharedMemorySize, SMEM_SZ);

    reset_kernel<<<(PAD_ROWS + 255) / 256, 256>>>();
    router_kernel<<<T_TOKENS / 8, 256>>>(x, noise, Wg, bg, Wn, bn);
    offsets_kernel<<<1, 32>>>();
    scatter_kernel<<<(T_TOKENS + 255) / 256, 256>>>();
    gather_split_kernel<<<PAD_ROWS, 128>>>(x);
    // total 16B-units per weight tensor: E*K*N/8 = 4,194,304 -> 16384 blocks of 256
    wsplit_kernel<<<16384, 256>>>(W1, 0);
    wsplit_kernel<<<16384, 256>>>(W2, 1);

    cudaMemsetAsync(out, 0, (size_t)out_size * sizeof(float));

    gemm_mma<0><<<dim3(NT1, MT_MAX), 256, SMEM_SZ>>>(b1, nullptr);
    gemm_mma<1><<<dim3(NT2, MT_MAX), 256, SMEM_SZ>>>(b2, out);
}

// round 10
// speedup vs baseline: 1.0010x; 1.0010x over previous
#include <cuda_runtime.h>
#include <cuda_fp16.h>
#include <math.h>
#include <stdint.h>

#define T_TOKENS 8192
#define D_DIM    1024
#define E_EXP    8
#define H_DIM    4096
#define MT_MAX   136
#define PAD_ROWS (MT_MAX * 128)
#define KC1      32              // D/32 k-chunks (phase 0)
#define KC2      128             // H/32 k-chunks (phase 1)
#define NT1      32              // H/128 n-tiles (phase 0)
#define NT2      8               // D/128 n-tiles (phase 1)
#define STG      24576           // bytes per pipeline stage: A_hi 8K | A_lo 8K | B 8K
#define SMEM_SZ  (4 * STG)       // 96 KB

// -------- device scratch (tile-contiguous fp16) --------
__device__ __align__(256) __half g_xg_hi[(size_t)PAD_ROWS * D_DIM];
__device__ __align__(256) __half g_xg_lo[(size_t)PAD_ROWS * D_DIM];
__device__ __align__(256) __half g_h_hi[(size_t)PAD_ROWS * H_DIM];
__device__ __align__(256) __half g_h_lo[(size_t)PAD_ROWS * H_DIM];
__device__ __align__(256) __half g_w1t[(size_t)E_EXP * D_DIM * H_DIM];
__device__ __align__(256) __half g_w2t[(size_t)E_EXP * D_DIM * H_DIM];

__device__ int   g_counts[E_EXP];
__device__ int   g_offsets[E_EXP];
__device__ int   g_cursors[E_EXP];
__device__ int   g_tok_e[T_TOKENS * 2];
__device__ float g_tok_g[T_TOKENS * 2];
__device__ int   g_assign_tok[PAD_ROWS];
__device__ float g_assign_gate[PAD_ROWS];
__device__ int   g_tile_e[MT_MAX];

// ---------------- PTX helpers (base-target sm_80+ features) ----------------
__device__ __forceinline__ uint32_t smem_u32(const void* p) {
    uint32_t a;
    asm("{ .reg .u64 t; cvta.to.shared.u64 t, %1; cvt.u32.u64 %0, t; }" : "=r"(a) : "l"(p));
    return a;
}
#define CP16(dst, src) \
    asm volatile("cp.async.cg.shared.global [%0], [%1], 16;" :: "r"(dst), "l"(src) : "memory")
#define CP_COMMIT() asm volatile("cp.async.commit_group;" ::: "memory")
#define CP_WAIT2()  asm volatile("cp.async.wait_group 2;" ::: "memory")

#define LDSM4(r0,r1,r2,r3,a) \
    asm volatile("ldmatrix.sync.aligned.m8n8.x4.shared.b16 {%0,%1,%2,%3},[%4];" \
        : "=r"(r0),"=r"(r1),"=r"(r2),"=r"(r3) : "r"(a))
#define LDSM4T(r0,r1,r2,r3,a) \
    asm volatile("ldmatrix.sync.aligned.m8n8.x4.trans.shared.b16 {%0,%1,%2,%3},[%4];" \
        : "=r"(r0),"=r"(r1),"=r"(r2),"=r"(r3) : "r"(a))

__device__ __forceinline__ void mma_f16(float* c, const uint32_t* a, const uint32_t* b) {
    asm volatile(
        "mma.sync.aligned.m16n8k16.row.col.f32.f16.f16.f32 "
        "{%0,%1,%2,%3},{%4,%5,%6,%7},{%8,%9},{%0,%1,%2,%3};"
        : "+f"(c[0]), "+f"(c[1]), "+f"(c[2]), "+f"(c[3])
        : "r"(a[0]), "r"(a[1]), "r"(a[2]), "r"(a[3]), "r"(b[0]), "r"(b[1]));
}

// split two fp32 into packed fp16 hi / fp16 lo (residual)
__device__ __forceinline__ void split2(float v0, float v1, uint32_t& hi, uint32_t& lo) {
    __half h0 = __float2half_rn(v0);
    __half h1 = __float2half_rn(v1);
    __half l0 = __float2half_rn(v0 - __half2float(h0));
    __half l1 = __float2half_rn(v1 - __half2float(h1));
    hi = ((uint32_t)__half_as_ushort(h1) << 16) | __half_as_ushort(h0);
    lo = ((uint32_t)__half_as_ushort(l1) << 16) | __half_as_ushort(l0);
}
// convert two fp32 to packed fp16
__device__ __forceinline__ uint32_t cvt2(float v0, float v1) {
    return ((uint32_t)__half_as_ushort(__float2half_rn(v1)) << 16)
         | __half_as_ushort(__float2half_rn(v0));
}

// ---------------- routing pipeline ----------------
__global__ void reset_kernel() {
    int i = blockIdx.x * blockDim.x + threadIdx.x;
    if (i < E_EXP) { g_counts[i] = 0; g_cursors[i] = 0; }
    if (i < PAD_ROWS) { g_assign_tok[i] = -1; g_assign_gate[i] = 0.f; }
}

__global__ void router_kernel(const float* __restrict__ x, const float* __restrict__ noise,
                              const float* __restrict__ Wg, const float* __restrict__ bg,
                              const float* __restrict__ Wn, const float* __restrict__ bn)
{
    __shared__ float sx[8][D_DIM];
    const int warp = threadIdx.x >> 5, lane = threadIdx.x & 31;
    const int t = blockIdx.x * 8 + warp;
    const float4* xr  = reinterpret_cast<const float4*>(x + (size_t)t * D_DIM);
    float4*       sxr = reinterpret_cast<float4*>(sx[warp]);
    for (int i = lane; i < D_DIM / 4; i += 32) sxr[i] = xr[i];
    __syncwarp();

    float lg[E_EXP], nz[E_EXP];
    #pragma unroll
    for (int e = 0; e < E_EXP; e++) {
        float ag = 0.f, an = 0.f;
        for (int d = lane; d < D_DIM; d += 32) {
            float xv = sx[warp][d];
            ag = fmaf(xv, Wg[d * E_EXP + e], ag);
            an = fmaf(xv, Wn[d * E_EXP + e], an);
        }
        #pragma unroll
        for (int o = 16; o > 0; o >>= 1) {
            ag += __shfl_down_sync(0xffffffffu, ag, o);
            an += __shfl_down_sync(0xffffffffu, an, o);
        }
        lg[e] = ag; nz[e] = an;
    }
    if (lane == 0) {
        float nv[E_EXP];
        #pragma unroll
        for (int e = 0; e < E_EXP; e++) {
            float z  = nz[e] + bn[e];
            float sp = fmaxf(z, 0.f) + log1pf(expf(-fabsf(z)));
            nv[e] = lg[e] + bg[e] + noise[(size_t)t * E_EXP + e] * sp;
        }
        int e1 = 0; float v1 = nv[0];
        #pragma unroll
        for (int e = 1; e < E_EXP; e++) if (nv[e] > v1) { v1 = nv[e]; e1 = e; }
        int e2 = -1; float v2 = -INFINITY;
        #pragma unroll
        for (int e = 0; e < E_EXP; e++) if (e != e1 && nv[e] > v2) { v2 = nv[e]; e2 = e; }
        float ex = expf(v2 - v1);
        g_tok_e[2*t+0] = e1;  g_tok_g[2*t+0] = 1.f / (1.f + ex);
        g_tok_e[2*t+1] = e2;  g_tok_g[2*t+1] = ex  / (1.f + ex);
        atomicAdd(&g_counts[e1], 1);
        atomicAdd(&g_counts[e2], 1);
    }
}

__global__ void offsets_kernel() {
    if (threadIdx.x == 0) {
        int po = 0, t = 0;
        #pragma unroll
        for (int e = 0; e < E_EXP; e++) {
            g_offsets[e] = po;
            int ntl = (g_counts[e] + 127) >> 7;
            for (int j = 0; j < ntl; j++) g_tile_e[t++] = e;
            po += ntl << 7;
        }
        for (; t < MT_MAX; t++) g_tile_e[t] = -1;
    }
}

__global__ void scatter_kernel() {
    int t = blockIdx.x * blockDim.x + threadIdx.x;
    if (t >= T_TOKENS) return;
    #pragma unroll
    for (int k = 0; k < 2; k++) {
        int e = g_tok_e[2*t+k];
        int pos = g_offsets[e] + atomicAdd(&g_cursors[e], 1);
        g_assign_tok[pos]  = t;
        g_assign_gate[pos] = g_tok_g[2*t+k];
    }
}

// gather x rows -> [mtile][kc<32][m<128][k<32] fp16 hi/lo (tile-contiguous)
__global__ void gather_split_kernel(const float* __restrict__ x) {
    int slot = blockIdx.x;
    int tok = g_assign_tok[slot];
    int mtile = slot >> 7, r = slot & 127;
    int t = threadIdx.x;                 // 16B-output unit: 8 k-elements
    float v[8];
    if (tok >= 0) {
        const float4* p = reinterpret_cast<const float4*>(x + (size_t)tok * D_DIM + t * 8);
        float4 a = p[0], b = p[1];
        v[0]=a.x; v[1]=a.y; v[2]=a.z; v[3]=a.w; v[4]=b.x; v[5]=b.y; v[6]=b.z; v[7]=b.w;
    } else {
        #pragma unroll
        for (int j = 0; j < 8; j++) v[j] = 0.f;
    }
    uint32_t hi[4], lo[4];
    #pragma unroll
    for (int p = 0; p < 4; p++) split2(v[2*p], v[2*p+1], hi[p], lo[p]);
    int kc = t >> 2, kin = (t & 3) * 8;
    size_t o = (((size_t)mtile * KC1 + kc) * 128 + r) * 32 + kin;
    *reinterpret_cast<uint4*>(g_xg_hi + o) = make_uint4(hi[0],hi[1],hi[2],hi[3]);
    *reinterpret_cast<uint4*>(g_xg_lo + o) = make_uint4(lo[0],lo[1],lo[2],lo[3]);
}

// W[e][K][N] -> [e][nt][kc][ki<32][n<128] fp16 (tile-contiguous convert)
__global__ void wsplit_kernel(const float* __restrict__ W, int which) {
    int NT   = which ? NT2 : NT1;
    int KC   = which ? KC2 : KC1;
    int Kdim = which ? H_DIM : D_DIM;
    int Ndim = which ? D_DIM : H_DIM;
    __half* dst = which ? g_w2t : g_w1t;

    size_t idx = (size_t)blockIdx.x * 256 + threadIdx.x;   // each: 8 n-elements
    int nu = idx & 15;             // 16 units per 128-n row
    size_t q = idx >> 4;
    int ki = q & 31; q >>= 5;
    int kc = (int)(q % KC); q /= KC;
    int nt = (int)(q % NT); int e = (int)(q / NT);
    if (e >= E_EXP) return;

    int k = kc * 32 + ki;
    const float* src = W + ((size_t)e * Kdim + k) * Ndim + nt * 128 + nu * 8;
    const float4* s4 = reinterpret_cast<const float4*>(src);
    float4 a = s4[0], b = s4[1];
    uint4 o4 = make_uint4(cvt2(a.x, a.y), cvt2(a.z, a.w), cvt2(b.x, b.y), cvt2(b.z, b.w));
    *reinterpret_cast<uint4*>(dst + idx * 8) = o4;
}

// ---------------- fp16x2 mma.sync grouped GEMM ----------------
// CTA: 128(M) x 128(N), K-chunk 32, 4-stage cp.async pipeline, 2 CTAs/SM.
// Stage layout: A_hi(8K) | A_lo(8K) | B(8K).
// A smem: [m<128][k<32], 64B rows, 16B-unit swizzle u^((m>>1)&3).
// B smem: [k<32][n<128], 256B rows, 16B-unit swizzle u^(k&7).
template<int PHASE>
__global__ __launch_bounds__(256, 2)
void gemm_mma(const float* __restrict__ bias, float* __restrict__ out)
{
    constexpr int KI = PHASE ? KC2 : KC1;
    constexpr int NT = PHASE ? NT2 : NT1;
    const int mtile = blockIdx.y;
    const int e = g_tile_e[mtile];
    if (e < 0) return;
    const int nt = blockIdx.x;

    extern __shared__ __align__(128) char smem[];
    const uint32_t sm0 = smem_u32(smem);
    const int tid = threadIdx.x, lane = tid & 31, w = tid >> 5;
    const int wm = (w & 3) * 32, wn = (w >> 2) * 64;

    const __half* Ah = PHASE ? g_h_hi : g_xg_hi;
    const __half* Al = PHASE ? g_h_lo : g_xg_lo;
    const __half* Bw = PHASE ? g_w2t  : g_w1t;
    const size_t abase = (size_t)mtile * KI * 4096;
    const size_t bbase = (size_t)(e * NT + nt) * KI * 4096;

    // cp.async dst offsets (loop-invariant per thread)
    uint32_t dA[2], dB[2];
    #pragma unroll
    for (int i = 0; i < 2; i++) {
        int idx = tid + 256 * i;
        int mA = idx >> 2, uA = idx & 3;
        dA[i] = mA * 64 + ((uA ^ ((mA >> 1) & 3)) << 4);
        int kB = idx >> 4, uB = idx & 15;
        dB[i] = kB * 256 + ((uB ^ (kB & 7)) << 4);
    }

    auto issue = [&](int c) {
        if (c < KI) {
            uint32_t sb = sm0 + (c & 3) * STG;
            size_t ao = abase + (size_t)c * 4096;
            size_t bo = bbase + (size_t)c * 4096;
            #pragma unroll
            for (int i = 0; i < 2; i++) {
                size_t el = (size_t)(tid + 256 * i) * 8;
                CP16(sb +         dA[i], Ah + ao + el);
                CP16(sb + 8192  + dA[i], Al + ao + el);
                CP16(sb + 16384 + dB[i], Bw + bo + el);
            }
        }
        CP_COMMIT();
    };

    // ldmatrix source offsets (per lane, precomputed)
    uint32_t offA[2][2], offB[4][2];
    {
        int j = lane >> 3, r = lane & 7;
        #pragma unroll
        for (int mt = 0; mt < 2; mt++)
            #pragma unroll
            for (int ks = 0; ks < 2; ks++) {
                int m = wm + mt * 16 + (j & 1) * 8 + r;
                int k = ks * 16 + (j >> 1) * 8;
                offA[mt][ks] = m * 64 + (((k >> 3) ^ ((m >> 1) & 3)) << 4);
            }
        #pragma unroll
        for (int nb = 0; nb < 4; nb++)
            #pragma unroll
            for (int ks = 0; ks < 2; ks++) {
                int k = ks * 16 + (j & 1) * 8 + r;
                int n = wn + nb * 16 + (j >> 1) * 8;
                offB[nb][ks] = k * 256 + (((n >> 3) ^ (k & 7)) << 4);
            }
    }

    float acc[2][8][4];
    #pragma unroll
    for (int a = 0; a < 2; a++)
        #pragma unroll
        for (int b = 0; b < 8; b++)
            #pragma unroll
            for (int c = 0; c < 4; c++) acc[a][b][c] = 0.f;

    issue(0); issue(1); issue(2);

    for (int i = 0; i < KI; i++) {
        CP_WAIT2();
        __syncthreads();
        issue(i + 3);
        uint32_t sb = sm0 + (i & 3) * STG;
        #pragma unroll
        for (int ks = 0; ks < 2; ks++) {
            uint32_t aH[2][4], aL[2][4], bF[8][2];
            #pragma unroll
            for (int mt = 0; mt < 2; mt++) {
                LDSM4(aH[mt][0], aH[mt][1], aH[mt][2], aH[mt][3], sb + offA[mt][ks]);
                LDSM4(aL[mt][0], aL[mt][1], aL[mt][2], aL[mt][3], sb + 8192 + offA[mt][ks]);
            }
            #pragma unroll
            for (int nb = 0; nb < 4; nb++)
                LDSM4T(bF[2*nb][0], bF[2*nb][1], bF[2*nb+1][0], bF[2*nb+1][1],
                       sb + 16384 + offB[nb][ks]);
            #pragma unroll
            for (int mt = 0; mt < 2; mt++)
                #pragma unroll
                for (int nb = 0; nb < 8; nb++) {
                    mma_f16(acc[mt][nb], aH[mt], bF[nb]);
                    mma_f16(acc[mt][nb], aL[mt], bF[nb]);
                }
        }
    }

    // ---------------- epilogue ----------------
    if (PHASE == 0) {
        // bias + relu + fp16-split -> g_h in phase-1 A layout [mtile][kc][m][k32]
        #pragma unroll
        for (int mt = 0; mt < 2; mt++) {
            int row0 = wm + mt * 16 + (lane >> 2);
            #pragma unroll
            for (int nb = 0; nb < 8; nb++) {
                int col = wn + nb * 8 + (lane & 3) * 2;
                int ng  = nt * 128 + col;
                float bv0 = __ldg(&bias[(size_t)e * H_DIM + ng]);
                float bv1 = __ldg(&bias[(size_t)e * H_DIM + ng + 1]);
                int kc2 = ng >> 5, kin = ng & 31;
                #pragma unroll
                for (int rr = 0; rr < 2; rr++) {
                    int m = row0 + rr * 8;
                    float v0 = fmaxf(acc[mt][nb][rr*2+0] + bv0, 0.f);
                    float v1 = fmaxf(acc[mt][nb][rr*2+1] + bv1, 0.f);
                    uint32_t ph, pl;
                    split2(v0, v1, ph, pl);
                    size_t o = (((size_t)mtile * KC2 + kc2) * 128 + m) * 32 + kin;
                    *reinterpret_cast<uint32_t*>(g_h_hi + o) = ph;
                    *reinterpret_cast<uint32_t*>(g_h_lo + o) = pl;
                }
            }
        }
    } else {
        // bias + gate + atomic combine into out
        #pragma unroll
        for (int mt = 0; mt < 2; mt++) {
            #pragma unroll
            for (int rr = 0; rr < 2; rr++) {
                int m = wm + mt * 16 + (lane >> 2) + rr * 8;
                int slot = mtile * 128 + m;
                int tok = __ldg(&g_assign_tok[slot]);
                if (tok < 0) continue;
                float gate = __ldg(&g_assign_gate[slot]);
                float* orow = out + (size_t)tok * D_DIM;
                #pragma unroll
                for (int nb = 0; nb < 8; nb++) {
                    int col = wn + nb * 8 + (lane & 3) * 2;
                    int ng  = nt * 128 + col;
                    float y0 = acc[mt][nb][rr*2+0] + __ldg(&bias[(size_t)e * D_DIM + ng]);
                    float y1 = acc[mt][nb][rr*2+1] + __ldg(&bias[(size_t)e * D_DIM + ng + 1]);
                    atomicAdd(&orow[ng],     gate * y0);
                    atomicAdd(&orow[ng + 1], gate * y1);
                }
            }
        }
    }
}

// ============================================================================
extern "C" void kernel_launch(void* const* d_in, const int* in_sizes, int n_in,
                              void* d_out, int out_size)
{
    const float* x     = (const float*)d_in[0];
    const float* noise = (const float*)d_in[1];
    const float* Wg    = (const float*)d_in[2];
    const float* bg    = (const float*)d_in[3];
    const float* Wn    = (const float*)d_in[4];
    const float* bn    = (const float*)d_in[5];
    const float* W1    = (const float*)d_in[6];
    const float* b1    = (const float*)d_in[7];
    const float* W2    = (const float*)d_in[8];
    const float* b2    = (const float*)d_in[9];
    float*       out   = (float*)d_out;

    cudaFuncSetAttribute(gemm_mma<0>, cudaFuncAttributeMaxDynamicSharedMemorySize, SMEM_SZ);
    cudaFuncSetAttribute(gemm_mma<1>, cudaFuncAttributeMaxDynamicSharedMemorySize, SMEM_SZ);

    reset_kernel<<<(PAD_ROWS + 255) / 256, 256>>>();
    router_kernel<<<T_TOKENS / 8, 256>>>(x, noise, Wg, bg, Wn, bn);
    offsets_kernel<<<1, 32>>>();
    scatter_kernel<<<(T_TOKENS + 255) / 256, 256>>>();
    gather_split_kernel<<<PAD_ROWS, 128>>>(x);
    // total 16B-units per weight tensor: E*K*N/8 = 4,194,304 -> 16384 blocks of 256
    wsplit_kernel<<<16384, 256>>>(W1, 0);
    wsplit_kernel<<<16384, 256>>>(W2, 1);

    cudaMemsetAsync(out, 0, (size_t)out_size * sizeof(float));

    gemm_mma<0><<<dim3(NT1, MT_MAX), 256, SMEM_SZ>>>(b1, nullptr);
    gemm_mma<1><<<dim3(NT2, MT_MAX), 256, SMEM_SZ>>>(b2, out);
}

// round 11
// speedup vs baseline: 1.0019x; 1.0010x over previous
#include <cuda_runtime.h>
#include <cuda_fp16.h>
#include <math.h>
#include <stdint.h>

#define T_TOKENS 8192
#define D_DIM    1024
#define E_EXP    8
#define H_DIM    4096
#define MT_MAX   136
#define PAD_ROWS (MT_MAX * 128)
#define KC1      32              // D/32 k-chunks (phase 0)
#define KC2      128             // H/32 k-chunks (phase 1)
#define NT1      32              // H/128 n-tiles (phase 0)
#define NT2      8               // D/128 n-tiles (phase 1)
#define STG      24576           // bytes per pipeline stage: A_hi 8K | A_lo 8K | B 8K
#define SMEM_SZ  (4 * STG)       // 96 KB

// -------- device scratch (tile-contiguous fp16) --------
__device__ __align__(256) __half g_xg_hi[(size_t)PAD_ROWS * D_DIM];
__device__ __align__(256) __half g_xg_lo[(size_t)PAD_ROWS * D_DIM];
__device__ __align__(256) __half g_h_hi[(size_t)PAD_ROWS * H_DIM];
__device__ __align__(256) __half g_h_lo[(size_t)PAD_ROWS * H_DIM];
__device__ __align__(256) __half g_w1t[(size_t)E_EXP * D_DIM * H_DIM];
__device__ __align__(256) __half g_w2t[(size_t)E_EXP * D_DIM * H_DIM];

__device__ int   g_counts[E_EXP];
__device__ int   g_offsets[E_EXP];
__device__ int   g_cursors[E_EXP];
__device__ int   g_tok_e[T_TOKENS * 2];
__device__ float g_tok_g[T_TOKENS * 2];
__device__ int   g_assign_tok[PAD_ROWS];
__device__ float g_assign_gate[PAD_ROWS];
__device__ int   g_tile_e[MT_MAX];

// ---------------- PTX helpers (base-target sm_80+ features) ----------------
__device__ __forceinline__ uint32_t smem_u32(const void* p) {
    uint32_t a;
    asm("{ .reg .u64 t; cvta.to.shared.u64 t, %1; cvt.u32.u64 %0, t; }" : "=r"(a) : "l"(p));
    return a;
}
#define CP16(dst, src) \
    asm volatile("cp.async.cg.shared.global [%0], [%1], 16;" :: "r"(dst), "l"(src) : "memory")
#define CP_COMMIT() asm volatile("cp.async.commit_group;" ::: "memory")
#define CP_WAIT2()  asm volatile("cp.async.wait_group 2;" ::: "memory")

#define LDSM4(r0,r1,r2,r3,a) \
    asm volatile("ldmatrix.sync.aligned.m8n8.x4.shared.b16 {%0,%1,%2,%3},[%4];" \
        : "=r"(r0),"=r"(r1),"=r"(r2),"=r"(r3) : "r"(a))
#define LDSM4T(r0,r1,r2,r3,a) \
    asm volatile("ldmatrix.sync.aligned.m8n8.x4.trans.shared.b16 {%0,%1,%2,%3},[%4];" \
        : "=r"(r0),"=r"(r1),"=r"(r2),"=r"(r3) : "r"(a))

__device__ __forceinline__ void mma_f16(float* c, const uint32_t* a, const uint32_t* b) {
    asm volatile(
        "mma.sync.aligned.m16n8k16.row.col.f32.f16.f16.f32 "
        "{%0,%1,%2,%3},{%4,%5,%6,%7},{%8,%9},{%0,%1,%2,%3};"
        : "+f"(c[0]), "+f"(c[1]), "+f"(c[2]), "+f"(c[3])
        : "r"(a[0]), "r"(a[1]), "r"(a[2]), "r"(a[3]), "r"(b[0]), "r"(b[1]));
}

// split two fp32 into packed fp16 hi / fp16 lo (residual)
__device__ __forceinline__ void split2(float v0, float v1, uint32_t& hi, uint32_t& lo) {
    __half h0 = __float2half_rn(v0);
    __half h1 = __float2half_rn(v1);
    __half l0 = __float2half_rn(v0 - __half2float(h0));
    __half l1 = __float2half_rn(v1 - __half2float(h1));
    hi = ((uint32_t)__half_as_ushort(h1) << 16) | __half_as_ushort(h0);
    lo = ((uint32_t)__half_as_ushort(l1) << 16) | __half_as_ushort(l0);
}
// convert two fp32 to packed fp16
__device__ __forceinline__ uint32_t cvt2(float v0, float v1) {
    return ((uint32_t)__half_as_ushort(__float2half_rn(v1)) << 16)
         | __half_as_ushort(__float2half_rn(v0));
}

// ---------------- routing pipeline ----------------
__global__ void reset_kernel() {
    int i = blockIdx.x * blockDim.x + threadIdx.x;
    if (i < E_EXP) { g_counts[i] = 0; g_cursors[i] = 0; }
    if (i < PAD_ROWS) { g_assign_tok[i] = -1; g_assign_gate[i] = 0.f; }
}

__global__ void router_kernel(const float* __restrict__ x, const float* __restrict__ noise,
                              const float* __restrict__ Wg, const float* __restrict__ bg,
                              const float* __restrict__ Wn, const float* __restrict__ bn)
{
    __shared__ float sx[8][D_DIM];
    const int warp = threadIdx.x >> 5, lane = threadIdx.x & 31;
    const int t = blockIdx.x * 8 + warp;
    const float4* xr  = reinterpret_cast<const float4*>(x + (size_t)t * D_DIM);
    float4*       sxr = reinterpret_cast<float4*>(sx[warp]);
    for (int i = lane; i < D_DIM / 4; i += 32) sxr[i] = xr[i];
    __syncwarp();

    float lg[E_EXP], nz[E_EXP];
    #pragma unroll
    for (int e = 0; e < E_EXP; e++) {
        float ag = 0.f, an = 0.f;
        for (int d = lane; d < D_DIM; d += 32) {
            float xv = sx[warp][d];
            ag = fmaf(xv, Wg[d * E_EXP + e], ag);
            an = fmaf(xv, Wn[d * E_EXP + e], an);
        }
        #pragma unroll
        for (int o = 16; o > 0; o >>= 1) {
            ag += __shfl_down_sync(0xffffffffu, ag, o);
            an += __shfl_down_sync(0xffffffffu, an, o);
        }
        lg[e] = ag; nz[e] = an;
    }
    if (lane == 0) {
        float nv[E_EXP];
        #pragma unroll
        for (int e = 0; e < E_EXP; e++) {
            float z  = nz[e] + bn[e];
            float sp = fmaxf(z, 0.f) + log1pf(expf(-fabsf(z)));
            nv[e] = lg[e] + bg[e] + noise[(size_t)t * E_EXP + e] * sp;
        }
        int e1 = 0; float v1 = nv[0];
        #pragma unroll
        for (int e = 1; e < E_EXP; e++) if (nv[e] > v1) { v1 = nv[e]; e1 = e; }
        int e2 = -1; float v2 = -INFINITY;
        #pragma unroll
        for (int e = 0; e < E_EXP; e++) if (e != e1 && nv[e] > v2) { v2 = nv[e]; e2 = e; }
        float ex = expf(v2 - v1);
        g_tok_e[2*t+0] = e1;  g_tok_g[2*t+0] = 1.f / (1.f + ex);
        g_tok_e[2*t+1] = e2;  g_tok_g[2*t+1] = ex  / (1.f + ex);
        atomicAdd(&g_counts[e1], 1);
        atomicAdd(&g_counts[e2], 1);
    }
}

__global__ void offsets_kernel() {
    if (threadIdx.x == 0) {
        int po = 0, t = 0;
        #pragma unroll
        for (int e = 0; e < E_EXP; e++) {
            g_offsets[e] = po;
            int ntl = (g_counts[e] + 127) >> 7;
            for (int j = 0; j < ntl; j++) g_tile_e[t++] = e;
            po += ntl << 7;
        }
        for (; t < MT_MAX; t++) g_tile_e[t] = -1;
    }
}

__global__ void scatter_kernel() {
    int t = blockIdx.x * blockDim.x + threadIdx.x;
    if (t >= T_TOKENS) return;
    #pragma unroll
    for (int k = 0; k < 2; k++) {
        int e = g_tok_e[2*t+k];
        int pos = g_offsets[e] + atomicAdd(&g_cursors[e], 1);
        g_assign_tok[pos]  = t;
        g_assign_gate[pos] = g_tok_g[2*t+k];
    }
}

// gather x rows -> [mtile][kc<32][m<128][k<32] fp16 hi/lo (tile-contiguous)
__global__ void gather_split_kernel(const float* __restrict__ x) {
    int slot = blockIdx.x;
    int tok = g_assign_tok[slot];
    int mtile = slot >> 7, r = slot & 127;
    int t = threadIdx.x;                 // 16B-output unit: 8 k-elements
    float v[8];
    if (tok >= 0) {
        const float4* p = reinterpret_cast<const float4*>(x + (size_t)tok * D_DIM + t * 8);
        float4 a = p[0], b = p[1];
        v[0]=a.x; v[1]=a.y; v[2]=a.z; v[3]=a.w; v[4]=b.x; v[5]=b.y; v[6]=b.z; v[7]=b.w;
    } else {
        #pragma unroll
        for (int j = 0; j < 8; j++) v[j] = 0.f;
    }
    uint32_t hi[4], lo[4];
    #pragma unroll
    for (int p = 0; p < 4; p++) split2(v[2*p], v[2*p+1], hi[p], lo[p]);
    int kc = t >> 2, kin = (t & 3) * 8;
    size_t o = (((size_t)mtile * KC1 + kc) * 128 + r) * 32 + kin;
    *reinterpret_cast<uint4*>(g_xg_hi + o) = make_uint4(hi[0],hi[1],hi[2],hi[3]);
    *reinterpret_cast<uint4*>(g_xg_lo + o) = make_uint4(lo[0],lo[1],lo[2],lo[3]);
}

// W[e][K][N] -> [e][nt][kc][ki<32][n<128] fp16 (tile-contiguous convert)
__global__ void wsplit_kernel(const float* __restrict__ W, int which) {
    int NT   = which ? NT2 : NT1;
    int KC   = which ? KC2 : KC1;
    int Kdim = which ? H_DIM : D_DIM;
    int Ndim = which ? D_DIM : H_DIM;
    __half* dst = which ? g_w2t : g_w1t;

    size_t idx = (size_t)blockIdx.x * 256 + threadIdx.x;   // each: 8 n-elements
    int nu = idx & 15;             // 16 units per 128-n row
    size_t q = idx >> 4;
    int ki = q & 31; q >>= 5;
    int kc = (int)(q % KC); q /= KC;
    int nt = (int)(q % NT); int e = (int)(q / NT);
    if (e >= E_EXP) return;

    int k = kc * 32 + ki;
    const float* src = W + ((size_t)e * Kdim + k) * Ndim + nt * 128 + nu * 8;
    const float4* s4 = reinterpret_cast<const float4*>(src);
    float4 a = s4[0], b = s4[1];
    uint4 o4 = make_uint4(cvt2(a.x, a.y), cvt2(a.z, a.w), cvt2(b.x, b.y), cvt2(b.z, b.w));
    *reinterpret_cast<uint4*>(dst + idx * 8) = o4;
}

// ---------------- fp16x2 mma.sync grouped GEMM ----------------
// CTA: 128(M) x 128(N), K-chunk 32, 4-stage cp.async pipeline, 2 CTAs/SM.
// Stage layout: A_hi(8K) | A_lo(8K) | B(8K).
// A smem: [m<128][k<32], 64B rows, 16B-unit swizzle u^((m>>1)&3).
// B smem: [k<32][n<128], 256B rows, 16B-unit swizzle u^(k&7).
template<int PHASE>
__global__ __launch_bounds__(256, 2)
void gemm_mma(const float* __restrict__ bias, float* __restrict__ out)
{
    constexpr int KI = PHASE ? KC2 : KC1;
    constexpr int NT = PHASE ? NT2 : NT1;
    const int mtile = blockIdx.y;
    const int e = g_tile_e[mtile];
    if (e < 0) return;
    const int nt = blockIdx.x;

    extern __shared__ __align__(128) char smem[];
    const uint32_t sm0 = smem_u32(smem);
    const int tid = threadIdx.x, lane = tid & 31, w = tid >> 5;
    const int wm = (w & 3) * 32, wn = (w >> 2) * 64;

    const __half* Ah = PHASE ? g_h_hi : g_xg_hi;
    const __half* Al = PHASE ? g_h_lo : g_xg_lo;
    const __half* Bw = PHASE ? g_w2t  : g_w1t;
    const size_t abase = (size_t)mtile * KI * 4096;
    const size_t bbase = (size_t)(e * NT + nt) * KI * 4096;

    // cp.async dst offsets (loop-invariant per thread)
    uint32_t dA[2], dB[2];
    #pragma unroll
    for (int i = 0; i < 2; i++) {
        int idx = tid + 256 * i;
        int mA = idx >> 2, uA = idx & 3;
        dA[i] = mA * 64 + ((uA ^ ((mA >> 1) & 3)) << 4);
        int kB = idx >> 4, uB = idx & 15;
        dB[i] = kB * 256 + ((uB ^ (kB & 7)) << 4);
    }

    auto issue = [&](int c) {
        if (c < KI) {
            uint32_t sb = sm0 + (c & 3) * STG;
            size_t ao = abase + (size_t)c * 4096;
            size_t bo = bbase + (size_t)c * 4096;
            #pragma unroll
            for (int i = 0; i < 2; i++) {
                size_t el = (size_t)(tid + 256 * i) * 8;
                CP16(sb +         dA[i], Ah + ao + el);
                CP16(sb + 8192  + dA[i], Al + ao + el);
                CP16(sb + 16384 + dB[i], Bw + bo + el);
            }
        }
        CP_COMMIT();
    };

    // ldmatrix source offsets (per lane, precomputed)
    uint32_t offA[2][2], offB[4][2];
    {
        int j = lane >> 3, r = lane & 7;
        #pragma unroll
        for (int mt = 0; mt < 2; mt++)
            #pragma unroll
            for (int ks = 0; ks < 2; ks++) {
                int m = wm + mt * 16 + (j & 1) * 8 + r;
                int k = ks * 16 + (j >> 1) * 8;
                offA[mt][ks] = m * 64 + (((k >> 3) ^ ((m >> 1) & 3)) << 4);
            }
        #pragma unroll
        for (int nb = 0; nb < 4; nb++)
            #pragma unroll
            for (int ks = 0; ks < 2; ks++) {
                int k = ks * 16 + (j & 1) * 8 + r;
                int n = wn + nb * 16 + (j >> 1) * 8;
                offB[nb][ks] = k * 256 + (((n >> 3) ^ (k & 7)) << 4);
            }
    }

    float acc[2][8][4];
    #pragma unroll
    for (int a = 0; a < 2; a++)
        #pragma unroll
        for (int b = 0; b < 8; b++)
            #pragma unroll
            for (int c = 0; c < 4; c++) acc[a][b][c] = 0.f;

    issue(0); issue(1); issue(2);

    for (int i = 0; i < KI; i++) {
        CP_WAIT2();
        __syncthreads();
        issue(i + 3);
        uint32_t sb = sm0 + (i & 3) * STG;
        #pragma unroll
        for (int ks = 0; ks < 2; ks++) {
            uint32_t aH[2][4], aL[2][4], bF[8][2];
            #pragma unroll
            for (int mt = 0; mt < 2; mt++) {
                LDSM4(aH[mt][0], aH[mt][1], aH[mt][2], aH[mt][3], sb + offA[mt][ks]);
                LDSM4(aL[mt][0], aL[mt][1], aL[mt][2], aL[mt][3], sb + 8192 + offA[mt][ks]);
            }
            #pragma unroll
            for (int nb = 0; nb < 4; nb++)
                LDSM4T(bF[2*nb][0], bF[2*nb][1], bF[2*nb+1][0], bF[2*nb+1][1],
                       sb + 16384 + offB[nb][ks]);
            #pragma unroll
            for (int mt = 0; mt < 2; mt++)
                #pragma unroll
                for (int nb = 0; nb < 8; nb++) {
                    mma_f16(acc[mt][nb], aH[mt], bF[nb]);
                    mma_f16(acc[mt][nb], aL[mt], bF[nb]);
                }
        }
    }

    // ---------------- epilogue ----------------
    if (PHASE == 0) {
        // bias + relu + fp16-split -> g_h in phase-1 A layout [mtile][kc][m][k32]
        #pragma unroll
        for (int mt = 0; mt < 2; mt++) {
            int row0 = wm + mt * 16 + (lane >> 2);
            #pragma unroll
            for (int nb = 0; nb < 8; nb++) {
                int col = wn + nb * 8 + (lane & 3) * 2;
                int ng  = nt * 128 + col;
                float bv0 = __ldg(&bias[(size_t)e * H_DIM + ng]);
                float bv1 = __ldg(&bias[(size_t)e * H_DIM + ng + 1]);
                int kc2 = ng >> 5, kin = ng & 31;
                #pragma unroll
                for (int rr = 0; rr < 2; rr++) {
                    int m = row0 + rr * 8;
                    float v0 = fmaxf(acc[mt][nb][rr*2+0] + bv0, 0.f);
                    float v1 = fmaxf(acc[mt][nb][rr*2+1] + bv1, 0.f);
                    uint32_t ph, pl;
                    split2(v0, v1, ph, pl);
                    size_t o = (((size_t)mtile * KC2 + kc2) * 128 + m) * 32 + kin;
                    *reinterpret_cast<uint32_t*>(g_h_hi + o) = ph;
                    *reinterpret_cast<uint32_t*>(g_h_lo + o) = pl;
                }
            }
        }
    } else {
        // bias + gate + atomic combine into out
        #pragma unroll
        for (int mt = 0; mt < 2; mt++) {
            #pragma unroll
            for (int rr = 0; rr < 2; rr++) {
                int m = wm + mt * 16 + (lane >> 2) + rr * 8;
                int slot = mtile * 128 + m;
                int tok = __ldg(&g_assign_tok[slot]);
                if (tok < 0) continue;
                float gate = __ldg(&g_assign_gate[slot]);
                float* orow = out + (size_t)tok * D_DIM;
                #pragma unroll
                for (int nb = 0; nb < 8; nb++) {
                    int col = wn + nb * 8 + (lane & 3) * 2;
                    int ng  = nt * 128 + col;
                    float y0 = acc[mt][nb][rr*2+0] + __ldg(&bias[(size_t)e * D_DIM + ng]);
                    float y1 = acc[mt][nb][rr*2+1] + __ldg(&bias[(size_t)e * D_DIM + ng + 1]);
                    atomicAdd(&orow[ng],     gate * y0);
                    atomicAdd(&orow[ng + 1], gate * y1);
                }
            }
        }
    }
}

// ============================================================================
extern "C" void kernel_launch(void* const* d_in, const int* in_sizes, int n_in,
                              void* d_out, int out_size)
{
    const float* x     = (const float*)d_in[0];
    const float* noise = (const float*)d_in[1];
    const float* Wg    = (const float*)d_in[2];
    const float* bg    = (const float*)d_in[3];
    const float* Wn    = (const float*)d_in[4];
    const float* bn    = (const float*)d_in[5];
    const float* W1    = (const float*)d_in[6];
    const float* b1    = (const float*)d_in[7];
    const float* W2    = (const float*)d_in[8];
    const float* b2    = (const float*)d_in[9];
    float*       out   = (float*)d_out;

    cudaFuncSetAttribute(gemm_mma<0>, cudaFuncAttributeMaxDynamicSharedMemorySize, SMEM_SZ);
    cudaFuncSetAttribute(gemm_mma<1>, cudaFuncAttributeMaxDynamicSharedMemorySize, SMEM_SZ);

    reset_kernel<<<(PAD_ROWS + 255) / 256, 256>>>();
    router_kernel<<<T_TOKENS / 8, 256>>>(x, noise, Wg, bg, Wn, bn);
    offsets_kernel<<<1, 32>>>();
    scatter_kernel<<<(T_TOKENS + 255) / 256, 256>>>();
    gather_split_kernel<<<PAD_ROWS, 128>>>(x);
    // total 16B-units per weight tensor: E*K*N/8 = 4,194,304 -> 16384 blocks of 256
    wsplit_kernel<<<16384, 256>>>(W1, 0);
    wsplit_kernel<<<16384, 256>>>(W2, 1);

    cudaMemsetAsync(out, 0, (size_t)out_size * sizeof(float));

    gemm_mma<0><<<dim3(NT1, MT_MAX), 256, SMEM_SZ>>>(b1, nullptr);
    gemm_mma<1><<<dim3(NT2, MT_MAX), 256, SMEM_SZ>>>(b2, out);
}